// round 8
// baseline (speedup 1.0000x reference)
#include <cuda_runtime.h>

// StatsQuantizer 4-bit fake-quant, 8192x8192 fp32.
// Forward math (gradient-only terms eliminated):
//   s    = 2 * mean(|w_row|)          (per row, axis=1)
//   c    = clamp(w/s, -clip/2, clip/2 - 1e-6)
//   out  = s * ((rint(c*8 - 0.5) + 0.5) / 8)
//
// R2 champion body (one row per iteration, 8x LDG.128 streamed to smem
// with the value consumed for |w| accumulation -> ptxas front-batches
// the loads; streaming cache hints) made PERSISTENT: grid = 740 CTAs
// (5/SM, matching R2's achieved residency), grid-stride over rows.
// Removes ~11 wave transitions + per-row CTA setup. No launch_bounds:
// R7 proved capping regs below ~47 destroys the batched-load schedule.

#define ROWS 8192
#define COLS 8192
#define TPB  256
#define V4_PER_THREAD (COLS / 4 / TPB)   // 8 float4 per thread
#define GRID 740                          // 148 SMs x 5 CTAs

__global__ void stats_quant_kernel(const float* __restrict__ w,
                                   const float* __restrict__ clip_val,
                                   float* __restrict__ out) {
    __shared__ float4 srow[COLS / 4];        // 32 KB
    __shared__ float warp_sums[TPB / 32];
    __shared__ float s_scale;

    const float hc = 0.5f * clip_val[0];
    const float lo = -hc;
    const float hi = hc - 1e-6f;

    for (int row = blockIdx.x; row < ROWS; row += GRID) {
        const float4* __restrict__ wrow =
            reinterpret_cast<const float4*>(w + (size_t)row * COLS);
        float4* __restrict__ orow =
            reinterpret_cast<float4*>(out + (size_t)row * COLS);

        // ---- Stream row global -> smem, accumulate |w| on the fly ----
        float asum = 0.0f;
#pragma unroll
        for (int i = 0; i < V4_PER_THREAD; i++) {
            const int idx = threadIdx.x + i * TPB;
            float4 v = __ldcs(&wrow[idx]);   // evict-first: no reuse in L2
            srow[idx] = v;
            asum += fabsf(v.x) + fabsf(v.y) + fabsf(v.z) + fabsf(v.w);
        }

        // ---- Block reduction: warp shfl then cross-warp via smem ----
#pragma unroll
        for (int off = 16; off > 0; off >>= 1)
            asum += __shfl_xor_sync(0xffffffffu, asum, off);
        if ((threadIdx.x & 31) == 0)
            warp_sums[threadIdx.x >> 5] = asum;
        __syncthreads();
        if (threadIdx.x == 0) {
            float t = 0.0f;
#pragma unroll
            for (int i = 0; i < TPB / 32; i++) t += warp_sums[i];
            // s = 2 * (t / 8192) = t / 4096
            s_scale = t * (1.0f / 4096.0f);
        }
        __syncthreads();

        const float s     = s_scale;
        const float invs  = 1.0f / s;
        const float sdiv8 = s * 0.125f;

        // ---- Quantize from smem, stream out ----
#pragma unroll
        for (int i = 0; i < V4_PER_THREAD; i++) {
            const int idx = threadIdx.x + i * TPB;
            float4 v = srow[idx];
            float4 r;
            float* pv = &v.x;
            float* pr = &r.x;
#pragma unroll
            for (int j = 0; j < 4; j++) {
                float c  = fminf(fmaxf(pv[j] * invs, lo), hi);
                float b4 = fmaf(c, 8.0f, -0.5f);
                pr[j]    = (rintf(b4) + 0.5f) * sdiv8;
            }
            __stcs(&orow[idx], r);           // evict-first store
        }

        // protect srow: stores above are fire-and-forget, but the next
        // iteration's loads overwrite smem other warps may still be reading
        __syncthreads();
    }
}

extern "C" void kernel_launch(void* const* d_in, const int* in_sizes, int n_in,
                              void* d_out, int out_size) {
    const float* weight   = (const float*)d_in[0];
    const float* clip_val = (const float*)d_in[1];
    float* out            = (float*)d_out;
    (void)in_sizes; (void)n_in; (void)out_size;

    stats_quant_kernel<<<GRID, TPB>>>(weight, clip_val, out);
}

// round 9
// speedup vs baseline: 1.0683x; 1.0683x over previous
#include <cuda_runtime.h>
#include <cstdint>

// StatsQuantizer 4-bit fake-quant, 8192x8192 fp32.
// Forward math (gradient-only terms eliminated):
//   s    = 2 * mean(|w_row|)          (per row, axis=1)
//   c    = clamp(w/s, -clip/2, clip/2 - 1e-6)
//   out  = s * ((rint(c*8 - 0.5) + 0.5) / 8)
//
// R2 champion read path (one CTA/row, 8x LDG.128 streamed to smem,
// consumed for the |w| sum -> ptxas front-batches the loads). Write
// path replaced: quantize IN PLACE in smem, then one cp.async.bulk
// (TMA) 32 KB burst store per row -> perfectly sequential full-line
// writes instead of per-thread STG.128 interleaved with reads.

#define ROWS 8192
#define COLS 8192
#define TPB  256
#define ROW_BYTES (COLS * 4)             // 32768
#define V4_PER_THREAD (COLS / 4 / TPB)   // 8 float4 per thread

__global__ void stats_quant_kernel(const float* __restrict__ w,
                                   const float* __restrict__ clip_val,
                                   float* __restrict__ out) {
    __shared__ alignas(128) float4 srow[COLS / 4];   // 32 KB
    __shared__ float warp_sums[TPB / 32];
    __shared__ float s_scale;

    const int row = blockIdx.x;
    const float4* __restrict__ wrow =
        reinterpret_cast<const float4*>(w + (size_t)row * COLS);

    // ---- Stream row global -> smem, accumulate |w| on the fly ----
    // (identical to the R2 champion load loop)
    float asum = 0.0f;
#pragma unroll
    for (int i = 0; i < V4_PER_THREAD; i++) {
        const int idx = threadIdx.x + i * TPB;
        float4 v = __ldcs(&wrow[idx]);       // evict-first: no reuse in L2
        srow[idx] = v;
        asum += fabsf(v.x) + fabsf(v.y) + fabsf(v.z) + fabsf(v.w);
    }

    // ---- Block reduction: warp shfl then cross-warp via smem ----
#pragma unroll
    for (int off = 16; off > 0; off >>= 1)
        asum += __shfl_xor_sync(0xffffffffu, asum, off);
    if ((threadIdx.x & 31) == 0)
        warp_sums[threadIdx.x >> 5] = asum;
    __syncthreads();
    if (threadIdx.x == 0) {
        float t = 0.0f;
#pragma unroll
        for (int i = 0; i < TPB / 32; i++) t += warp_sums[i];
        // s = 2 * (t / 8192) = t / 4096
        s_scale = t * (1.0f / 4096.0f);
    }
    __syncthreads();

    const float s     = s_scale;
    const float invs  = 1.0f / s;
    const float hc    = 0.5f * clip_val[0];
    const float lo    = -hc;
    const float hi    = hc - 1e-6f;
    const float sdiv8 = s * 0.125f;

    // ---- Quantize in place in smem ----
#pragma unroll
    for (int i = 0; i < V4_PER_THREAD; i++) {
        const int idx = threadIdx.x + i * TPB;
        float4 v = srow[idx];
        float4 r;
        float* pv = &v.x;
        float* pr = &r.x;
#pragma unroll
        for (int j = 0; j < 4; j++) {
            float c  = fminf(fmaxf(pv[j] * invs, lo), hi);
            float b4 = fmaf(c, 8.0f, -0.5f);
            pr[j]    = (rintf(b4) + 0.5f) * sdiv8;
        }
        srow[idx] = r;
    }
    __syncthreads();

    // ---- One TMA bulk store: 32 KB smem -> global, full-line burst ----
    if (threadIdx.x == 0) {
        const uint32_t src = (uint32_t)__cvta_generic_to_shared(srow);
        float* dst = out + (size_t)row * COLS;
        asm volatile("fence.proxy.async.shared::cta;" ::: "memory");
        asm volatile("cp.async.bulk.global.shared::cta.bulk_group "
                     "[%0], [%1], %2;"
                     :: "l"(dst), "r"(src), "r"(ROW_BYTES) : "memory");
        asm volatile("cp.async.bulk.commit_group;" ::: "memory");
        asm volatile("cp.async.bulk.wait_group 0;" ::: "memory");
    }
}

extern "C" void kernel_launch(void* const* d_in, const int* in_sizes, int n_in,
                              void* d_out, int out_size) {
    const float* weight   = (const float*)d_in[0];
    const float* clip_val = (const float*)d_in[1];
    float* out            = (float*)d_out;
    (void)in_sizes; (void)n_in; (void)out_size;

    stats_quant_kernel<<<ROWS, TPB>>>(weight, clip_val, out);
}

// round 10
// speedup vs baseline: 1.1728x; 1.0978x over previous
#include <cuda_runtime.h>

// StatsQuantizer 4-bit fake-quant, 8192x8192 fp32.
// Forward math (gradient-only terms eliminated):
//   s    = 2 * mean(|w_row|)          (per row, axis=1)
//   c    = clamp(w/s, -clip/2, clip/2 - 1e-6)
//   out  = s * ((rint(c*8 - 0.5) + 0.5) / 8)
//
// Two-pass with L2 reuse, no smem staging:
//   pass 1: pure load+reduce (8x __ldcg float4 -> FADD chain). Nothing
//           but the loads in the loop -> ptxas front-batches all 8
//           LDG.128 (the schedule class that wins: R1/R2, regs>=47).
//   pass 2: re-read the row via __ldcs (L2 hit: ~24 MB resident working
//           set << 126 MB L2; distinct intrinsic blocks CSE), quantize,
//           stream out with __stcs.
// DRAM traffic stays at the 512 MiB floor; pass-2 reads come from L2,
// so DRAM serves a clean pass-1 read stream + write stream.

#define ROWS 8192
#define COLS 8192
#define TPB  256
#define V4_PER_THREAD (COLS / 4 / TPB)   // 8 float4 per thread

__global__ void stats_quant_kernel(const float* __restrict__ w,
                                   const float* __restrict__ clip_val,
                                   float* __restrict__ out) {
    __shared__ float warp_sums[TPB / 32];
    __shared__ float s_scale;

    const int row = blockIdx.x;
    const float4* __restrict__ wrow =
        reinterpret_cast<const float4*>(w + (size_t)row * COLS);
    float4* __restrict__ orow =
        reinterpret_cast<float4*>(out + (size_t)row * COLS);

    // ---- pass 1: pure load + |w| reduce (front-batched LDG.128) ----
    float asum = 0.0f;
#pragma unroll
    for (int i = 0; i < V4_PER_THREAD; i++) {
        float4 v = __ldcg(&wrow[threadIdx.x + i * TPB]);  // cache at L2
        asum += fabsf(v.x) + fabsf(v.y) + fabsf(v.z) + fabsf(v.w);
    }

    // ---- block reduction: warp shfl then cross-warp via smem ----
#pragma unroll
    for (int off = 16; off > 0; off >>= 1)
        asum += __shfl_xor_sync(0xffffffffu, asum, off);
    if ((threadIdx.x & 31) == 0)
        warp_sums[threadIdx.x >> 5] = asum;
    __syncthreads();
    if (threadIdx.x == 0) {
        float t = 0.0f;
#pragma unroll
        for (int i = 0; i < TPB / 32; i++) t += warp_sums[i];
        // s = 2 * (t / 8192) = t / 4096
        s_scale = t * (1.0f / 4096.0f);
    }
    __syncthreads();

    const float s     = s_scale;
    const float invs  = 1.0f / s;
    const float hc    = 0.5f * clip_val[0];
    const float lo    = -hc;
    const float hi    = hc - 1e-6f;
    const float sdiv8 = s * 0.125f;

    // ---- pass 2: re-read from L2, quantize, stream out ----
#pragma unroll
    for (int i = 0; i < V4_PER_THREAD; i++) {
        const int idx = threadIdx.x + i * TPB;
        float4 v = __ldcs(&wrow[idx]);       // L2 hit; evict after use
        float4 r;
        float* pv = &v.x;
        float* pr = &r.x;
#pragma unroll
        for (int j = 0; j < 4; j++) {
            float c  = fminf(fmaxf(pv[j] * invs, lo), hi);
            float b4 = fmaf(c, 8.0f, -0.5f);
            pr[j]    = (rintf(b4) + 0.5f) * sdiv8;
        }
        __stcs(&orow[idx], r);               // evict-first store
    }
}

extern "C" void kernel_launch(void* const* d_in, const int* in_sizes, int n_in,
                              void* d_out, int out_size) {
    const float* weight   = (const float*)d_in[0];
    const float* clip_val = (const float*)d_in[1];
    float* out            = (float*)d_out;
    (void)in_sizes; (void)n_in; (void)out_size;

    stats_quant_kernel<<<ROWS, TPB>>>(weight, clip_val, out);
}